// round 9
// baseline (speedup 1.0000x reference)
#include <cuda_runtime.h>

// ---------------------------------------------------------------------------
// CubicHermite2d — two-pass cubic Hermite (dx = 1).
//   result = h00*y[I] + h10*m[I] + h01*y[I+1] + h11*m[I+1]
//   m[0] = y1-y0; m[N-1] = y[N-1]-y[N-2]; m[i] = 0.5*(y[i+1]-y[i-1])
//   I = clamp(ceil(v)-1, 0, N-2)   == searchsorted(x0[1:-1], v, 'left')
// Weights are computed ONCE per block by a cooperative prelude into smem
// arrays (compute-once-then-array-read, matching the proven k_weights
// dataflow) — no separate weights kernel, no weight L2 traffic.
// pass1: 8 signal rows per block in smem, weights reused across rows.
// pass2: 8 consecutive qy per thread, tap rows deduped in registers; __stcs.
// ---------------------------------------------------------------------------

#define TMP_ELEMS (32u * 512u * 1024u)   // B*H*Nx intermediate [B*H, Nx]
#define P1_ROWS 8
#define P1_WMAX 512
#define P1_QCH  1024     // x-weight smem chunk
#define P2_G    8

__device__ float g_tmp[TMP_ELEMS];

__device__ __forceinline__ void hermite_h(float v, int N, int* Iout, float4* hout) {
    int I = (int)ceilf(v) - 1;          // searchsorted-left on arange
    I = max(0, min(I, N - 2));
    float t  = v - (float)I;
    float t2 = t * t;
    float t3 = t2 * t;
    *Iout = I;
    *hout = make_float4(1.0f - 3.0f * t2 + 2.0f * t3,   // h00
                        t - 2.0f * t2 + t3,             // h10
                        3.0f * t2 - 2.0f * t3,          // h01
                        t3 - t2);                       // h11
}

// Pass 1: block = P1_ROWS consecutive (b,h) rows in smem. The block first
// evaluates the x-query weights into smem (one eval per query, cooperative),
// then the main loop reads them as arrays — reused across all 8 rows.
__global__ __launch_bounds__(256) void k_pass1(const float* __restrict__ sig,
                                               const float* __restrict__ xs,
                                               int W, int Nx, int nRows) {
    __shared__ float  s[P1_ROWS][P1_WMAX + 1];
    __shared__ int    s_ix[P1_QCH];
    __shared__ float4 s_hx[P1_QCH];

    const int tid   = threadIdx.x;
    const int rows0 = blockIdx.x * P1_ROWS;
    const int rcnt  = min(P1_ROWS, nRows - rows0);

    if (W <= P1_WMAX) {
        for (int idx = tid; idx < rcnt * W; idx += 256) {
            int r = idx / W, c = idx - r * W;
            s[r][c] = sig[(size_t)(rows0 + r) * W + c];
        }

        for (int qb = 0; qb < Nx; qb += P1_QCH) {
            const int qcnt = min(P1_QCH, Nx - qb);
            // weight prelude: compute once into smem
            for (int q = tid; q < qcnt; q += 256)
                hermite_h(xs[qb + q], W, &s_ix[q], &s_hx[q]);
            __syncthreads();

            for (int q0 = 0; q0 < qcnt; q0 += 256) {
                int q = q0 + tid;
                if (q < qcnt) {
                    int    I = s_ix[q];
                    float4 h = s_hx[q];
                    bool xlo = (I == 0);
                    bool xhi = (I == W - 2);
                    int cm = max(I - 1, 0);
                    int cp = min(I + 2, W - 1);
                    #pragma unroll
                    for (int r = 0; r < P1_ROWS; r++) {
                        if (r < rcnt) {
                            float ym  = s[r][cm];
                            float ylo = s[r][I];
                            float yhi = s[r][I + 1];
                            float yp  = s[r][cp];
                            float mlo = xlo ? (yhi - ylo) : 0.5f * (yhi - ym);
                            float mhi = xhi ? (yhi - ylo) : 0.5f * (yp - ylo);
                            g_tmp[(size_t)(rows0 + r) * Nx + (qb + q)] =
                                h.x * ylo + h.y * mlo + h.z * yhi + h.w * mhi;
                        }
                    }
                }
            }
            __syncthreads();
        }
    } else {                               // generic fallback (never hit at W=512)
        for (int qb = 0; qb < Nx; qb += P1_QCH) {
            const int qcnt = min(P1_QCH, Nx - qb);
            for (int q = tid; q < qcnt; q += 256)
                hermite_h(xs[qb + q], W, &s_ix[q], &s_hx[q]);
            __syncthreads();
            for (int r = 0; r < rcnt; r++) {
                const float* rp = sig + (size_t)(rows0 + r) * W;
                for (int q = tid; q < qcnt; q += 256) {
                    int    I = s_ix[q];
                    float4 h = s_hx[q];
                    float ym  = rp[max(I - 1, 0)];
                    float ylo = rp[I];
                    float yhi = rp[I + 1];
                    float yp  = rp[min(I + 2, W - 1)];
                    float mlo = (I == 0)     ? (yhi - ylo) : 0.5f * (yhi - ym);
                    float mhi = (I == W - 2) ? (yhi - ylo) : 0.5f * (yp - ylo);
                    g_tmp[(size_t)(rows0 + r) * Nx + (qb + q)] =
                        h.x * ylo + h.y * mlo + h.z * yhi + h.w * mhi;
                }
            }
            __syncthreads();
        }
    }
}

__device__ __forceinline__ float4 fetch_row(int r,
                                            int i0, int i1, int i2, int i3,
                                            float4 v0, float4 v1, float4 v2, float4 v3,
                                            const float4* __restrict__ tp,
                                            int nx4, int qx4) {
    if (r == i0) return v0;
    if (r == i1) return v1;
    if (r == i2) return v2;
    if (r == i3) return v3;
    return tp[(size_t)r * nx4 + qx4];
}

// Pass 2: one thread = one float4 column x P2_G consecutive qy. Block prelude
// computes its P2_G y-weights once into smem. Sorted ys => adjacent qy share
// tap rows; dedupe against previous qy's rows in registers (warp-uniform).
__global__ __launch_bounds__(256) void k_pass2(float* __restrict__ out,
                                               const float* __restrict__ ys,
                                               int H, int Nx, int Ny) {
    __shared__ int    s_iy[P2_G];
    __shared__ float4 s_hy[P2_G];

    const int nx4 = Nx >> 2;
    const int b   = blockIdx.y;
    const int qy0 = blockIdx.x * P2_G;

    if (threadIdx.x < P2_G && qy0 + threadIdx.x < Ny)
        hermite_h(ys[qy0 + threadIdx.x], H, &s_iy[threadIdx.x], &s_hy[threadIdx.x]);
    __syncthreads();

    const float4* tp = reinterpret_cast<const float4*>(g_tmp) + (size_t)b * H * nx4;
    float4* op = reinterpret_cast<float4*>(out) + (size_t)b * Ny * nx4;

    for (int qx4 = threadIdx.x; qx4 < nx4; qx4 += blockDim.x) {
        int i0 = -1, i1 = -1, i2 = -1, i3 = -1;
        float4 v0 = make_float4(0.f, 0.f, 0.f, 0.f), v1 = v0, v2 = v0, v3 = v0;

        #pragma unroll
        for (int g = 0; g < P2_G; g++) {
            int qy = qy0 + g;
            if (qy >= Ny) break;
            int    I = s_iy[g];
            float4 h = s_hy[g];
            int R0 = max(I - 1, 0);
            int R1 = I;
            int R2 = I + 1;
            int R3 = min(I + 2, H - 1);

            float4 n0 = fetch_row(R0, i0, i1, i2, i3, v0, v1, v2, v3, tp, nx4, qx4);
            float4 n1 = fetch_row(R1, i0, i1, i2, i3, v0, v1, v2, v3, tp, nx4, qx4);
            float4 n2 = fetch_row(R2, i0, i1, i2, i3, v0, v1, v2, v3, tp, nx4, qx4);
            float4 n3 = fetch_row(R3, i0, i1, i2, i3, v0, v1, v2, v3, tp, nx4, qx4);

            bool loE = (I == 0);
            bool hiE = (I == H - 2);
            float4 o;
            {
                float mlo = loE ? (n2.x - n1.x) : 0.5f * (n2.x - n0.x);
                float mhi = hiE ? (n2.x - n1.x) : 0.5f * (n3.x - n1.x);
                o.x = h.x * n1.x + h.y * mlo + h.z * n2.x + h.w * mhi;
            }
            {
                float mlo = loE ? (n2.y - n1.y) : 0.5f * (n2.y - n0.y);
                float mhi = hiE ? (n2.y - n1.y) : 0.5f * (n3.y - n1.y);
                o.y = h.x * n1.y + h.y * mlo + h.z * n2.y + h.w * mhi;
            }
            {
                float mlo = loE ? (n2.z - n1.z) : 0.5f * (n2.z - n0.z);
                float mhi = hiE ? (n2.z - n1.z) : 0.5f * (n3.z - n1.z);
                o.z = h.x * n1.z + h.y * mlo + h.z * n2.z + h.w * mhi;
            }
            {
                float mlo = loE ? (n2.w - n1.w) : 0.5f * (n2.w - n0.w);
                float mhi = hiE ? (n2.w - n1.w) : 0.5f * (n3.w - n1.w);
                o.w = h.x * n1.w + h.y * mlo + h.z * n2.w + h.w * mhi;
            }
            __stcs(&op[(size_t)qy * nx4 + qx4], o);   // streaming: protect g_tmp in L2

            i0 = R0; i1 = R1; i2 = R2; i3 = R3;
            v0 = n0; v1 = n1; v2 = n2; v3 = n3;
        }
    }
}

extern "C" void kernel_launch(void* const* d_in, const int* in_sizes, int n_in,
                              void* d_out, int out_size) {
    const float* sig = (const float*)d_in[0];
    // d_in[1] = x1 (arange, dx=1), d_in[2] = x2 (arange, dx=1)
    const float* xs  = (const float*)d_in[3];
    const float* ys  = (const float*)d_in[4];

    int W  = in_sizes[1];
    int H  = in_sizes[2];
    int Nx = in_sizes[3];
    int Ny = in_sizes[4];
    int B  = in_sizes[0] / (W * H);
    int nRows = B * H;

    k_pass1<<<(nRows + P1_ROWS - 1) / P1_ROWS, 256>>>(sig, xs, W, Nx, nRows);

    dim3 g2((Ny + P2_G - 1) / P2_G, B);
    k_pass2<<<g2, 256>>>((float*)d_out, ys, H, Nx, Ny);
}

// round 10
// speedup vs baseline: 1.0022x; 1.0022x over previous
#include <cuda_runtime.h>

// ---------------------------------------------------------------------------
// CubicHermite2d — two-pass cubic Hermite (dx = 1).
//   result = h00*y[I] + h10*m[I] + h01*y[I+1] + h11*m[I+1]
//   m[0] = y1-y0; m[N-1] = y[N-1]-y[N-2]; m[i] = 0.5*(y[i+1]-y[i-1])
//   I = clamp(ceil(v)-1, 0, N-2)   == searchsorted(x0[1:-1], v, 'left')
// pass1: 8 signal rows per block in smem; weights computed once per block
//        into smem (compute-once-then-array-read, proven dataflow).
// pass2: issue-count-optimized — warp-uniform SHIFT dedup over sorted qy
//        (d = I - Iprev in {0,1,2,else}) + two batches per block sharing all
//        uniform logic; __stcs output stores.
// ---------------------------------------------------------------------------

#define TMP_ELEMS (32u * 512u * 1024u)   // B*H*Nx intermediate [B*H, Nx]
#define P1_ROWS 8
#define P1_WMAX 512
#define P1_QCH  1024
#define P2_G    8

__device__ float g_tmp[TMP_ELEMS];

__device__ __forceinline__ void hermite_h(float v, int N, int* Iout, float4* hout) {
    int I = (int)ceilf(v) - 1;          // searchsorted-left on arange
    I = max(0, min(I, N - 2));
    float t  = v - (float)I;
    float t2 = t * t;
    float t3 = t2 * t;
    *Iout = I;
    *hout = make_float4(1.0f - 3.0f * t2 + 2.0f * t3,   // h00
                        t - 2.0f * t2 + t3,             // h10
                        3.0f * t2 - 2.0f * t3,          // h01
                        t3 - t2);                       // h11
}

// Pass 1: unchanged from the passing R9 version.
__global__ __launch_bounds__(256) void k_pass1(const float* __restrict__ sig,
                                               const float* __restrict__ xs,
                                               int W, int Nx, int nRows) {
    __shared__ float  s[P1_ROWS][P1_WMAX + 1];
    __shared__ int    s_ix[P1_QCH];
    __shared__ float4 s_hx[P1_QCH];

    const int tid   = threadIdx.x;
    const int rows0 = blockIdx.x * P1_ROWS;
    const int rcnt  = min(P1_ROWS, nRows - rows0);

    if (W <= P1_WMAX) {
        for (int idx = tid; idx < rcnt * W; idx += 256) {
            int r = idx / W, c = idx - r * W;
            s[r][c] = sig[(size_t)(rows0 + r) * W + c];
        }
        for (int qb = 0; qb < Nx; qb += P1_QCH) {
            const int qcnt = min(P1_QCH, Nx - qb);
            for (int q = tid; q < qcnt; q += 256)
                hermite_h(xs[qb + q], W, &s_ix[q], &s_hx[q]);
            __syncthreads();

            for (int q0 = 0; q0 < qcnt; q0 += 256) {
                int q = q0 + tid;
                if (q < qcnt) {
                    int    I = s_ix[q];
                    float4 h = s_hx[q];
                    bool xlo = (I == 0);
                    bool xhi = (I == W - 2);
                    int cm = max(I - 1, 0);
                    int cp = min(I + 2, W - 1);
                    #pragma unroll
                    for (int r = 0; r < P1_ROWS; r++) {
                        if (r < rcnt) {
                            float ym  = s[r][cm];
                            float ylo = s[r][I];
                            float yhi = s[r][I + 1];
                            float yp  = s[r][cp];
                            float mlo = xlo ? (yhi - ylo) : 0.5f * (yhi - ym);
                            float mhi = xhi ? (yhi - ylo) : 0.5f * (yp - ylo);
                            g_tmp[(size_t)(rows0 + r) * Nx + (qb + q)] =
                                h.x * ylo + h.y * mlo + h.z * yhi + h.w * mhi;
                        }
                    }
                }
            }
            __syncthreads();
        }
    } else {                               // generic fallback (never hit at W=512)
        for (int qb = 0; qb < Nx; qb += P1_QCH) {
            const int qcnt = min(P1_QCH, Nx - qb);
            for (int q = tid; q < qcnt; q += 256)
                hermite_h(xs[qb + q], W, &s_ix[q], &s_hx[q]);
            __syncthreads();
            for (int r = 0; r < rcnt; r++) {
                const float* rp = sig + (size_t)(rows0 + r) * W;
                for (int q = tid; q < qcnt; q += 256) {
                    int    I = s_ix[q];
                    float4 h = s_hx[q];
                    float ym  = rp[max(I - 1, 0)];
                    float ylo = rp[I];
                    float yhi = rp[I + 1];
                    float yp  = rp[min(I + 2, W - 1)];
                    float mlo = (I == 0)     ? (yhi - ylo) : 0.5f * (yhi - ym);
                    float mhi = (I == W - 2) ? (yhi - ylo) : 0.5f * (yp - ylo);
                    g_tmp[(size_t)(rows0 + r) * Nx + (qb + q)] =
                        h.x * ylo + h.y * mlo + h.z * yhi + h.w * mhi;
                }
            }
            __syncthreads();
        }
    }
}

// Literal hermite combine — byte-identical expressions to the passing kernel.
__device__ __forceinline__ float4 eval4(float4 n0, float4 n1, float4 n2, float4 n3,
                                        float4 h, bool loE, bool hiE) {
    float4 o;
    {
        float mlo = loE ? (n2.x - n1.x) : 0.5f * (n2.x - n0.x);
        float mhi = hiE ? (n2.x - n1.x) : 0.5f * (n3.x - n1.x);
        o.x = h.x * n1.x + h.y * mlo + h.z * n2.x + h.w * mhi;
    }
    {
        float mlo = loE ? (n2.y - n1.y) : 0.5f * (n2.y - n0.y);
        float mhi = hiE ? (n2.y - n1.y) : 0.5f * (n3.y - n1.y);
        o.y = h.x * n1.y + h.y * mlo + h.z * n2.y + h.w * mhi;
    }
    {
        float mlo = loE ? (n2.z - n1.z) : 0.5f * (n2.z - n0.z);
        float mhi = hiE ? (n2.z - n1.z) : 0.5f * (n3.z - n1.z);
        o.z = h.x * n1.z + h.y * mlo + h.z * n2.z + h.w * mhi;
    }
    {
        float mlo = loE ? (n2.w - n1.w) : 0.5f * (n2.w - n0.w);
        float mhi = hiE ? (n2.w - n1.w) : 0.5f * (n3.w - n1.w);
        o.w = h.x * n1.w + h.y * mlo + h.z * n2.w + h.w * mhi;
    }
    return o;
}

// Pass 2: one thread = one float4 column x P2_G consecutive qy x TWO batches
// (ba, bb = ba + ceil(B/2)). Sorted ys => window shift d = I - Iprev >= 0;
// warp-uniform switch on d in {0,1,2,else} replaces the compare-chain dedup.
// Shift validity (all window rows, incl. clamped ends):
//   d==1: newR0=I-1=prevR1, newR1=I=prevR2, newR2=I+1=prevR3 (I<=H-2 => no clamp);
//         newR3 = prevR3 only if both clamp at H-1.
//   d==2: newR0=I-1=prevR2, newR1=I=prevR3(=min(I,H-1)=I).
__global__ __launch_bounds__(256) void k_pass2(float* __restrict__ out,
                                               const float* __restrict__ ys,
                                               int H, int Nx, int Ny,
                                               int B, int Bhalf) {
    __shared__ int    s_iy[P2_G];
    __shared__ float4 s_hy[P2_G];

    const int nx4 = Nx >> 2;
    const int qy0 = blockIdx.x * P2_G;
    const int ba  = blockIdx.y;
    const int bb  = blockIdx.y + Bhalf;
    const bool hasB = (bb < B);

    if (threadIdx.x < P2_G && qy0 + threadIdx.x < Ny)
        hermite_h(ys[qy0 + threadIdx.x], H, &s_iy[threadIdx.x], &s_hy[threadIdx.x]);
    __syncthreads();

    const float4* tpa = reinterpret_cast<const float4*>(g_tmp) + (size_t)ba * H * nx4;
    const float4* tpb = reinterpret_cast<const float4*>(g_tmp) + (size_t)bb * H * nx4;
    float4* opa = reinterpret_cast<float4*>(out) + (size_t)ba * Ny * nx4;
    float4* opb = reinterpret_cast<float4*>(out) + (size_t)bb * Ny * nx4;

    for (int qx4 = threadIdx.x; qx4 < nx4; qx4 += blockDim.x) {
        int iPrev = -0x40000000, r3Prev = -1;
        float4 z = make_float4(0.f, 0.f, 0.f, 0.f);
        float4 va0 = z, va1 = z, va2 = z, va3 = z;
        float4 vb0 = z, vb1 = z, vb2 = z, vb3 = z;

        #pragma unroll
        for (int g = 0; g < P2_G; g++) {
            int qy = qy0 + g;
            if (qy >= Ny) break;
            int    I = s_iy[g];
            float4 h = s_hy[g];
            int R2 = I + 1;
            int R3 = min(I + 2, H - 1);
            int d  = I - iPrev;

            float4 na0, na1, na2, na3, nb0, nb1, nb2, nb3;
            if (d == 0) {
                na0 = va0; na1 = va1; na2 = va2; na3 = va3;
                nb0 = vb0; nb1 = vb1; nb2 = vb2; nb3 = vb3;
            } else if (d == 1) {
                na0 = va1; na1 = va2; na2 = va3;
                nb0 = vb1; nb1 = vb2; nb2 = vb3;
                if (R3 == r3Prev) { na3 = va3; nb3 = vb3; }
                else {
                    na3 = tpa[(size_t)R3 * nx4 + qx4];
                    nb3 = hasB ? tpb[(size_t)R3 * nx4 + qx4] : na3;
                }
            } else if (d == 2) {
                na0 = va2; na1 = va3;
                nb0 = vb2; nb1 = vb3;
                na2 = tpa[(size_t)R2 * nx4 + qx4];
                nb2 = hasB ? tpb[(size_t)R2 * nx4 + qx4] : na2;
                if (R3 == R2) { na3 = na2; nb3 = nb2; }
                else {
                    na3 = tpa[(size_t)R3 * nx4 + qx4];
                    nb3 = hasB ? tpb[(size_t)R3 * nx4 + qx4] : na3;
                }
            } else {
                int R0 = max(I - 1, 0);
                na0 = tpa[(size_t)R0 * nx4 + qx4];
                na1 = tpa[(size_t)I  * nx4 + qx4];
                na2 = tpa[(size_t)R2 * nx4 + qx4];
                na3 = (R3 == R2) ? na2 : tpa[(size_t)R3 * nx4 + qx4];
                if (hasB) {
                    nb0 = tpb[(size_t)R0 * nx4 + qx4];
                    nb1 = tpb[(size_t)I  * nx4 + qx4];
                    nb2 = tpb[(size_t)R2 * nx4 + qx4];
                    nb3 = (R3 == R2) ? nb2 : tpb[(size_t)R3 * nx4 + qx4];
                } else { nb0 = na0; nb1 = na1; nb2 = na2; nb3 = na3; }
            }

            bool loE = (I == 0);
            bool hiE = (I == H - 2);
            float4 oa = eval4(na0, na1, na2, na3, h, loE, hiE);
            __stcs(&opa[(size_t)qy * nx4 + qx4], oa);
            if (hasB) {
                float4 ob = eval4(nb0, nb1, nb2, nb3, h, loE, hiE);
                __stcs(&opb[(size_t)qy * nx4 + qx4], ob);
            }

            iPrev = I; r3Prev = R3;
            va0 = na0; va1 = na1; va2 = na2; va3 = na3;
            vb0 = nb0; vb1 = nb1; vb2 = nb2; vb3 = nb3;
        }
    }
}

extern "C" void kernel_launch(void* const* d_in, const int* in_sizes, int n_in,
                              void* d_out, int out_size) {
    const float* sig = (const float*)d_in[0];
    // d_in[1] = x1 (arange, dx=1), d_in[2] = x2 (arange, dx=1)
    const float* xs  = (const float*)d_in[3];
    const float* ys  = (const float*)d_in[4];

    int W  = in_sizes[1];
    int H  = in_sizes[2];
    int Nx = in_sizes[3];
    int Ny = in_sizes[4];
    int B  = in_sizes[0] / (W * H);
    int nRows = B * H;
    int Bhalf = (B + 1) / 2;

    k_pass1<<<(nRows + P1_ROWS - 1) / P1_ROWS, 256>>>(sig, xs, W, Nx, nRows);

    dim3 g2((Ny + P2_G - 1) / P2_G, Bhalf);
    k_pass2<<<g2, 256>>>((float*)d_out, ys, H, Nx, Ny, B, Bhalf);
}

// round 11
// speedup vs baseline: 1.0681x; 1.0658x over previous
#include <cuda_runtime.h>

// ---------------------------------------------------------------------------
// CubicHermite2d — two-pass cubic Hermite (dx = 1).
//   result = h00*y[I] + h10*m[I] + h01*y[I+1] + h11*m[I+1]
//   m[0] = y1-y0; m[N-1] = y[N-1]-y[N-2]; m[i] = 0.5*(y[i+1]-y[i-1])
//   I = clamp(ceil(v)-1, 0, N-2)   == searchsorted(x0[1:-1], v, 'left')
// pass1: 8 signal rows per block in smem; weights computed once per block
//        into smem (compute-once-then-array-read, proven dataflow).
// pass2: SINGLE batch, warp-uniform SHIFT dedup over sorted qy
//        (d = I - Iprev in {0,1,2,else}), P2_G=16 chain; __stcs stores.
//        (R10 showed dual-batch costs 33% occupancy for no net gain.)
// ---------------------------------------------------------------------------

#define TMP_ELEMS (32u * 512u * 1024u)   // B*H*Nx intermediate [B*H, Nx]
#define P1_ROWS 8
#define P1_WMAX 512
#define P1_QCH  1024
#define P2_G    16

__device__ float g_tmp[TMP_ELEMS];

__device__ __forceinline__ void hermite_h(float v, int N, int* Iout, float4* hout) {
    int I = (int)ceilf(v) - 1;          // searchsorted-left on arange
    I = max(0, min(I, N - 2));
    float t  = v - (float)I;
    float t2 = t * t;
    float t3 = t2 * t;
    *Iout = I;
    *hout = make_float4(1.0f - 3.0f * t2 + 2.0f * t3,   // h00
                        t - 2.0f * t2 + t3,             // h10
                        3.0f * t2 - 2.0f * t3,          // h01
                        t3 - t2);                       // h11
}

// Pass 1: unchanged from the passing R9/R10 version.
__global__ __launch_bounds__(256) void k_pass1(const float* __restrict__ sig,
                                               const float* __restrict__ xs,
                                               int W, int Nx, int nRows) {
    __shared__ float  s[P1_ROWS][P1_WMAX + 1];
    __shared__ int    s_ix[P1_QCH];
    __shared__ float4 s_hx[P1_QCH];

    const int tid   = threadIdx.x;
    const int rows0 = blockIdx.x * P1_ROWS;
    const int rcnt  = min(P1_ROWS, nRows - rows0);

    if (W <= P1_WMAX) {
        for (int idx = tid; idx < rcnt * W; idx += 256) {
            int r = idx / W, c = idx - r * W;
            s[r][c] = sig[(size_t)(rows0 + r) * W + c];
        }
        for (int qb = 0; qb < Nx; qb += P1_QCH) {
            const int qcnt = min(P1_QCH, Nx - qb);
            for (int q = tid; q < qcnt; q += 256)
                hermite_h(xs[qb + q], W, &s_ix[q], &s_hx[q]);
            __syncthreads();

            for (int q0 = 0; q0 < qcnt; q0 += 256) {
                int q = q0 + tid;
                if (q < qcnt) {
                    int    I = s_ix[q];
                    float4 h = s_hx[q];
                    bool xlo = (I == 0);
                    bool xhi = (I == W - 2);
                    int cm = max(I - 1, 0);
                    int cp = min(I + 2, W - 1);
                    #pragma unroll
                    for (int r = 0; r < P1_ROWS; r++) {
                        if (r < rcnt) {
                            float ym  = s[r][cm];
                            float ylo = s[r][I];
                            float yhi = s[r][I + 1];
                            float yp  = s[r][cp];
                            float mlo = xlo ? (yhi - ylo) : 0.5f * (yhi - ym);
                            float mhi = xhi ? (yhi - ylo) : 0.5f * (yp - ylo);
                            g_tmp[(size_t)(rows0 + r) * Nx + (qb + q)] =
                                h.x * ylo + h.y * mlo + h.z * yhi + h.w * mhi;
                        }
                    }
                }
            }
            __syncthreads();
        }
    } else {                               // generic fallback (never hit at W=512)
        for (int qb = 0; qb < Nx; qb += P1_QCH) {
            const int qcnt = min(P1_QCH, Nx - qb);
            for (int q = tid; q < qcnt; q += 256)
                hermite_h(xs[qb + q], W, &s_ix[q], &s_hx[q]);
            __syncthreads();
            for (int r = 0; r < rcnt; r++) {
                const float* rp = sig + (size_t)(rows0 + r) * W;
                for (int q = tid; q < qcnt; q += 256) {
                    int    I = s_ix[q];
                    float4 h = s_hx[q];
                    float ym  = rp[max(I - 1, 0)];
                    float ylo = rp[I];
                    float yhi = rp[I + 1];
                    float yp  = rp[min(I + 2, W - 1)];
                    float mlo = (I == 0)     ? (yhi - ylo) : 0.5f * (yhi - ym);
                    float mhi = (I == W - 2) ? (yhi - ylo) : 0.5f * (yp - ylo);
                    g_tmp[(size_t)(rows0 + r) * Nx + (qb + q)] =
                        h.x * ylo + h.y * mlo + h.z * yhi + h.w * mhi;
                }
            }
            __syncthreads();
        }
    }
}

// Literal hermite combine — byte-identical expressions to the passing kernel.
__device__ __forceinline__ float4 eval4(float4 n0, float4 n1, float4 n2, float4 n3,
                                        float4 h, bool loE, bool hiE) {
    float4 o;
    {
        float mlo = loE ? (n2.x - n1.x) : 0.5f * (n2.x - n0.x);
        float mhi = hiE ? (n2.x - n1.x) : 0.5f * (n3.x - n1.x);
        o.x = h.x * n1.x + h.y * mlo + h.z * n2.x + h.w * mhi;
    }
    {
        float mlo = loE ? (n2.y - n1.y) : 0.5f * (n2.y - n0.y);
        float mhi = hiE ? (n2.y - n1.y) : 0.5f * (n3.y - n1.y);
        o.y = h.x * n1.y + h.y * mlo + h.z * n2.y + h.w * mhi;
    }
    {
        float mlo = loE ? (n2.z - n1.z) : 0.5f * (n2.z - n0.z);
        float mhi = hiE ? (n2.z - n1.z) : 0.5f * (n3.z - n1.z);
        o.z = h.x * n1.z + h.y * mlo + h.z * n2.z + h.w * mhi;
    }
    {
        float mlo = loE ? (n2.w - n1.w) : 0.5f * (n2.w - n0.w);
        float mhi = hiE ? (n2.w - n1.w) : 0.5f * (n3.w - n1.w);
        o.w = h.x * n1.w + h.y * mlo + h.z * n2.w + h.w * mhi;
    }
    return o;
}

// Pass 2: one thread = one float4 column x P2_G consecutive qy, one batch.
// Sorted ys => window shift d = I - Iprev >= 0; warp-uniform switch on
// d in {0,1,2,else}. Shift validity (incl. clamped ends):
//   d==1: newR0=I-1=prevR1, newR1=I=prevR2, newR2=I+1=prevR3 (no clamp, I<=H-2);
//         newR3 = prevR3 only if both clamp at H-1.
//   d==2: newR0=I-1=prevR2, newR1=I=prevR3(=min(I,H-1)=I).
__global__ __launch_bounds__(256) void k_pass2(float* __restrict__ out,
                                               const float* __restrict__ ys,
                                               int H, int Nx, int Ny) {
    __shared__ int    s_iy[P2_G];
    __shared__ float4 s_hy[P2_G];

    const int nx4 = Nx >> 2;
    const int qy0 = blockIdx.x * P2_G;
    const int b   = blockIdx.y;

    if (threadIdx.x < P2_G && qy0 + threadIdx.x < Ny)
        hermite_h(ys[qy0 + threadIdx.x], H, &s_iy[threadIdx.x], &s_hy[threadIdx.x]);
    __syncthreads();

    const float4* tp = reinterpret_cast<const float4*>(g_tmp) + (size_t)b * H * nx4;
    float4* op = reinterpret_cast<float4*>(out) + (size_t)b * Ny * nx4;

    for (int qx4 = threadIdx.x; qx4 < nx4; qx4 += blockDim.x) {
        int iPrev = -0x40000000, r3Prev = -1;
        float4 z = make_float4(0.f, 0.f, 0.f, 0.f);
        float4 v0 = z, v1 = z, v2 = z, v3 = z;

        #pragma unroll
        for (int g = 0; g < P2_G; g++) {
            int qy = qy0 + g;
            if (qy >= Ny) break;
            int    I = s_iy[g];
            float4 h = s_hy[g];
            int R2 = I + 1;
            int R3 = min(I + 2, H - 1);
            int d  = I - iPrev;

            float4 n0, n1, n2, n3;
            if (d == 0) {
                n0 = v0; n1 = v1; n2 = v2; n3 = v3;
            } else if (d == 1) {
                n0 = v1; n1 = v2; n2 = v3;
                n3 = (R3 == r3Prev) ? v3 : tp[(size_t)R3 * nx4 + qx4];
            } else if (d == 2) {
                n0 = v2; n1 = v3;
                n2 = tp[(size_t)R2 * nx4 + qx4];
                n3 = (R3 == R2) ? n2 : tp[(size_t)R3 * nx4 + qx4];
            } else {
                int R0 = max(I - 1, 0);
                n0 = tp[(size_t)R0 * nx4 + qx4];
                n1 = tp[(size_t)I  * nx4 + qx4];
                n2 = tp[(size_t)R2 * nx4 + qx4];
                n3 = (R3 == R2) ? n2 : tp[(size_t)R3 * nx4 + qx4];
            }

            float4 o = eval4(n0, n1, n2, n3, h, I == 0, I == H - 2);
            __stcs(&op[(size_t)qy * nx4 + qx4], o);   // streaming: protect g_tmp in L2

            iPrev = I; r3Prev = R3;
            v0 = n0; v1 = n1; v2 = n2; v3 = n3;
        }
    }
}

extern "C" void kernel_launch(void* const* d_in, const int* in_sizes, int n_in,
                              void* d_out, int out_size) {
    const float* sig = (const float*)d_in[0];
    // d_in[1] = x1 (arange, dx=1), d_in[2] = x2 (arange, dx=1)
    const float* xs  = (const float*)d_in[3];
    const float* ys  = (const float*)d_in[4];

    int W  = in_sizes[1];
    int H  = in_sizes[2];
    int Nx = in_sizes[3];
    int Ny = in_sizes[4];
    int B  = in_sizes[0] / (W * H);
    int nRows = B * H;

    k_pass1<<<(nRows + P1_ROWS - 1) / P1_ROWS, 256>>>(sig, xs, W, Nx, nRows);

    dim3 g2((Ny + P2_G - 1) / P2_G, B);
    k_pass2<<<g2, 256>>>((float*)d_out, ys, H, Nx, Ny);
}